// round 8
// baseline (speedup 1.0000x reference)
#include <cuda_runtime.h>
#include <cuda_bf16.h>
#include <cstdint>

// Problem constants
#define S_LEN 2048
#define B_SZ  128
#define H_SZ  128
#define G_SZ  384   // 3*H
#define C_SZ  10
#define TCH_T 16    // timesteps per GEMM CTA

// Scratch: xp (input projections, reused by both layers) and y0 (layer-0 output seq)
__device__ float g_xp[(size_t)S_LEN * B_SZ * G_SZ];   // [(t*B + b)*3H + g]
__device__ float g_y0[(size_t)S_LEN * B_SZ * H_SZ];   // [(t*B + b)*H + j]

// ---- packed dual-fp32 helpers -------------------------------------------
__device__ __forceinline__ unsigned long long fma2(unsigned long long a,
                                                   unsigned long long b,
                                                   unsigned long long c) {
    unsigned long long d;
    asm("fma.rn.f32x2 %0, %1, %2, %3;" : "=l"(d) : "l"(a), "l"(b), "l"(c));
    return d;
}
__device__ __forceinline__ unsigned long long add2(unsigned long long a,
                                                   unsigned long long b) {
    unsigned long long d;
    asm("add.rn.f32x2 %0, %1, %2;" : "=l"(d) : "l"(a), "l"(b));
    return d;
}
__device__ __forceinline__ float lo32(unsigned long long v) {
    return __uint_as_float((unsigned)(v & 0xffffffffull));
}
__device__ __forceinline__ float hi32(unsigned long long v) {
    return __uint_as_float((unsigned)(v >> 32));
}

// ---- mma.sync / ldmatrix helpers (plain sm_80+ features, no 'a'-gating) ---
__device__ __forceinline__ uint32_t smem_u32(const void* p) {
    uint32_t a;
    asm("{ .reg .u64 t; cvta.to.shared.u64 t, %1; cvt.u32.u64 %0, t; }"
        : "=r"(a) : "l"(p));
    return a;
}
__device__ __forceinline__ void ldmx4(uint32_t* r, uint32_t addr) {
    asm volatile("ldmatrix.sync.aligned.m8n8.x4.shared.b16 {%0,%1,%2,%3}, [%4];"
                 : "=r"(r[0]), "=r"(r[1]), "=r"(r[2]), "=r"(r[3]) : "r"(addr));
}
__device__ __forceinline__ void mma_bf16(float* c, const uint32_t* a,
                                         uint32_t b0, uint32_t b1) {
    asm volatile(
        "mma.sync.aligned.m16n8k16.row.col.f32.bf16.bf16.f32 "
        "{%0,%1,%2,%3}, {%4,%5,%6,%7}, {%8,%9}, {%0,%1,%2,%3};"
        : "+f"(c[0]), "+f"(c[1]), "+f"(c[2]), "+f"(c[3])
        : "r"(a[0]), "r"(a[1]), "r"(a[2]), "r"(a[3]), "r"(b0), "r"(b1));
}

// Split one float4 into bf16 hi + lo pairs (packed as uint2 = 4 bf16)
__device__ __forceinline__ void split4(float4 v, uint2& hi, uint2& lo) {
    __nv_bfloat162 h01 = __floats2bfloat162_rn(v.x, v.y);
    __nv_bfloat162 h23 = __floats2bfloat162_rn(v.z, v.w);
    const float r0 = v.x - __bfloat162float(h01.x);
    const float r1 = v.y - __bfloat162float(h01.y);
    const float r2 = v.z - __bfloat162float(h23.x);
    const float r3 = v.w - __bfloat162float(h23.y);
    __nv_bfloat162 l01 = __floats2bfloat162_rn(r0, r1);
    __nv_bfloat162 l23 = __floats2bfloat162_rn(r2, r3);
    hi = make_uint2(*reinterpret_cast<uint32_t*>(&h01), *reinterpret_cast<uint32_t*>(&h23));
    lo = make_uint2(*reinterpret_cast<uint32_t*>(&l01), *reinterpret_cast<uint32_t*>(&l23));
}

// SMEM layout (bytes): bias + 4 bf16 tiles [128 rows x 128 cols], pitch 272 B
#define PITCHB 272
#define TILEB  (128 * PITCHB)          // 34816
#define SM_BIAS 0
#define SM_XHI  512
#define SM_XLO  (SM_XHI + TILEB)
#define SM_WHI  (SM_XLO + TILEB)
#define SM_WLO  (SM_WHI + TILEB)
#define SM_TOT  (SM_WLO + TILEB)       // 139776

// ---------------------------------------------------------------------------
// Tensor-core input-projection GEMM via mma.sync — unchanged from R7 (proven).
// ---------------------------------------------------------------------------
__global__ __launch_bounds__(256, 1)
void gemm_mma_kernel(const float* __restrict__ in,
                     const float* __restrict__ W,
                     const float* __restrict__ bias,
                     float* __restrict__ out,
                     long strideB, long strideT)
{
    extern __shared__ __align__(16) char smem[];
    const uint32_t sb = smem_u32(smem);
    float* sbias = reinterpret_cast<float*>(smem + SM_BIAS);

    const int tid  = threadIdx.x;
    const int w    = tid >> 5;
    const int lane = tid & 31;
    const int tbase = blockIdx.x * TCH_T;
    const int g0    = blockIdx.y * 128;

    if (tid < 128) sbias[tid] = bias[g0 + tid];
    for (int i = tid; i < 128 * 32; i += 256) {
        const int row = i >> 5, c4 = i & 31;
        const float4 v = *reinterpret_cast<const float4*>(
            W + (size_t)(g0 + row) * H_SZ + c4 * 4);
        uint2 hi, lo;
        split4(v, hi, lo);
        const int off = row * PITCHB + c4 * 8;
        *reinterpret_cast<uint2*>(smem + SM_WHI + off) = hi;
        *reinterpret_cast<uint2*>(smem + SM_WLO + off) = lo;
    }

    const int mBase = (w & 1) * 64;
    const int nBase = (w >> 1) * 32;

    uint32_t aoff[4];
#pragma unroll
    for (int mt = 0; mt < 4; mt++)
        aoff[mt] = (uint32_t)((mBase + mt * 16 + (lane & 15)) * PITCHB
                              + (lane >> 4) * 16);
    uint32_t boff[2];
#pragma unroll
    for (int nt2 = 0; nt2 < 2; nt2++) {
        const int rt = lane & 7, tl = lane >> 3;
        const int n = nBase + nt2 * 16 + ((tl >> 1) << 3) + rt;
        boff[nt2] = (uint32_t)(n * PITCHB + (tl & 1) * 16);
    }

    for (int tt = 0; tt < TCH_T; tt++) {
        const int t = tbase + tt;

        for (int i = tid; i < 128 * 32; i += 256) {
            const int row = i >> 5, c4 = i & 31;
            const float4 v = *reinterpret_cast<const float4*>(
                in + (size_t)row * strideB + (size_t)t * strideT + c4 * 4);
            uint2 hi, lo;
            split4(v, hi, lo);
            const int off = row * PITCHB + c4 * 8;
            *reinterpret_cast<uint2*>(smem + SM_XHI + off) = hi;
            *reinterpret_cast<uint2*>(smem + SM_XLO + off) = lo;
        }
        __syncthreads();

        float acc[4][4][4];
#pragma unroll
        for (int mt = 0; mt < 4; mt++)
#pragma unroll
            for (int nt = 0; nt < 4; nt++)
#pragma unroll
                for (int e = 0; e < 4; e++) acc[mt][nt][e] = 0.0f;

#pragma unroll
        for (int s = 0; s < 3; s++) {
            const uint32_t aS = sb + (s == 2 ? SM_XLO : SM_XHI);
            const uint32_t bS = sb + (s == 1 ? SM_WLO : SM_WHI);
#pragma unroll
            for (int k16 = 0; k16 < 8; k16++) {
                const uint32_t kb = (uint32_t)(k16 * 32);
                uint32_t a[4][4], b[2][4];
#pragma unroll
                for (int mt = 0; mt < 4; mt++) ldmx4(a[mt], aS + aoff[mt] + kb);
#pragma unroll
                for (int nt2 = 0; nt2 < 2; nt2++) ldmx4(b[nt2], bS + boff[nt2] + kb);
#pragma unroll
                for (int mt = 0; mt < 4; mt++)
#pragma unroll
                    for (int nt = 0; nt < 4; nt++)
                        mma_bf16(acc[mt][nt], a[mt],
                                 b[nt >> 1][(nt & 1) * 2], b[nt >> 1][(nt & 1) * 2 + 1]);
            }
        }

        const int mrow = lane >> 2;
        const int ncol = (lane & 3) * 2;
#pragma unroll
        for (int mt = 0; mt < 4; mt++) {
#pragma unroll
            for (int nt = 0; nt < 4; nt++) {
                const int col = nBase + nt * 8 + ncol;
                const float bv0 = sbias[col], bv1 = sbias[col + 1];
                const int row0 = mBase + mt * 16 + mrow;
                float* p0 = out + ((size_t)t * B_SZ + row0) * G_SZ + g0 + col;
                float* p1 = p0 + (size_t)8 * G_SZ;
                *reinterpret_cast<float2*>(p0) =
                    make_float2(acc[mt][nt][0] + bv0, acc[mt][nt][1] + bv1);
                *reinterpret_cast<float2*>(p1) =
                    make_float2(acc[mt][nt][2] + bv0, acc[mt][nt][3] + bv1);
            }
        }
        __syncthreads();
    }
}

// ---------------------------------------------------------------------------
// Recurrent scan, quarter-split: 512 threads, tid = 4*j + p.
// Thread owns the p-th QUARTER (32 elems = 8 ulonglong2) of all three gate
// rows for output j. Quarters combined via 2-round butterfly shfl (xor 1, 2).
// 4 warps/SMSP (vs 2 before) -> same fma2 pipe floor, 2x latency hiding.
// x roles: p0 holds xr, p1 holds xz, p2 holds xn (one float each).
// Gate math: p0 does r+tanh+h-update; p1 does z (shfl'd to p0).
// ---------------------------------------------------------------------------
__global__ __launch_bounds__(512, 1)
void recur_kernel(const float* __restrict__ xp,
                  const float* __restrict__ W_hh,
                  const float* __restrict__ b_hh,
                  int write_y,
                  const float* __restrict__ W_out,
                  const float* __restrict__ b_out,
                  float* __restrict__ out)
{
    __shared__ __align__(16) float h_s[2][H_SZ];

    const int b   = blockIdx.x;
    const int tid = threadIdx.x;
    const int j   = tid >> 2;
    const int p   = tid & 3;

    // Weight quarter-rows -> registers (3 x 16 u64 = 96 regs of weights)
    unsigned long long wr[16], wz[16], wn[16];
    {
        const unsigned long long* rp = reinterpret_cast<const unsigned long long*>(
            W_hh + (size_t)j * H_SZ + p * 32);
        const unsigned long long* zp = reinterpret_cast<const unsigned long long*>(
            W_hh + (size_t)(H_SZ + j) * H_SZ + p * 32);
        const unsigned long long* np = reinterpret_cast<const unsigned long long*>(
            W_hh + (size_t)(2 * H_SZ + j) * H_SZ + p * 32);
#pragma unroll
        for (int i = 0; i < 16; i++) { wr[i] = rp[i]; wz[i] = zp[i]; wn[i] = np[i]; }
    }
    const float br = b_hh[j];
    const float bz = b_hh[H_SZ + j];
    const float bn = b_hh[2 * H_SZ + j];

    // One x value per thread, role by p: p0->xr, p1->xz, p2->xn, p3 unused
    const float* xb = xp + (size_t)b * G_SZ;
    const int xoff = (p < 3) ? (p * H_SZ + j) : j;
    float xme = __ldg(xb + xoff);

    float hreg = 0.0f;
    if (tid < H_SZ) h_s[0][tid] = 0.0f;
    __syncthreads();

    float* y0p = g_y0 + (size_t)b * H_SZ + j;

    for (int t = 0; t < S_LEN; t++) {
        const int cur = t & 1;
        const int nxt = cur ^ 1;

        // Prefetch next step's x (consumed next iteration -> latency hidden)
        float nxme = 0.0f;
        if (t + 1 < S_LEN)
            nxme = __ldg(xb + (size_t)(t + 1) * B_SZ * G_SZ + xoff);

        // Quarter-dots: 3 gates x 32 elems = 8 ulonglong2, 6 chains
        const ulonglong2* hq =
            reinterpret_cast<const ulonglong2*>(&h_s[cur][p * 32]);
        unsigned long long ar0 = 0ull, ar1 = 0ull;
        unsigned long long az0 = 0ull, az1 = 0ull;
        unsigned long long an0 = 0ull, an1 = 0ull;
#pragma unroll
        for (int i = 0; i < 8; i++) {
            const ulonglong2 q = hq[i];
            ar0 = fma2(q.x, wr[2 * i + 0], ar0);
            ar1 = fma2(q.y, wr[2 * i + 1], ar1);
            az0 = fma2(q.x, wz[2 * i + 0], az0);
            az1 = fma2(q.y, wz[2 * i + 1], az1);
            an0 = fma2(q.x, wn[2 * i + 0], an0);
            an1 = fma2(q.y, wn[2 * i + 1], an1);
        }
        const unsigned long long sr2 = add2(ar0, ar1);
        const unsigned long long sz2 = add2(az0, az1);
        const unsigned long long sn2 = add2(an0, an1);
        float sr = lo32(sr2) + hi32(sr2);
        float sz = lo32(sz2) + hi32(sz2);
        float sn = lo32(sn2) + hi32(sn2);

        // Butterfly combine over the 4-lane group (lanes 4j..4j+3)
        sr += __shfl_xor_sync(0xffffffffu, sr, 1);
        sz += __shfl_xor_sync(0xffffffffu, sz, 1);
        sn += __shfl_xor_sync(0xffffffffu, sn, 1);
        sr += __shfl_xor_sync(0xffffffffu, sr, 2);
        sz += __shfl_xor_sync(0xffffffffu, sz, 2);
        sn += __shfl_xor_sync(0xffffffffu, sn, 2);

        // p0 needs xn (held by p2): shfl across xor 2
        const float xn0 = __shfl_xor_sync(0xffffffffu, xme, 2);

        // z on p1 (xme == xz there), shfl'd to p0; r on p0 (xme == xr there)
        const float pz = xme + sz + bz;
        const float zg = 1.0f / (1.0f + __expf(-pz));
        const float z  = __shfl_xor_sync(0xffffffffu, zg, 1);

        if (p == 0) {
            const float pr = xme + sr + br;
            const float rg = 1.0f / (1.0f + __expf(-pr));
            const float ag = fmaf(rg, sn + bn, xn0);
            const float sg = 1.0f / (1.0f + __expf(-2.0f * ag));
            const float n  = fmaf(2.0f, sg, -1.0f);           // tanh(ag)
            const float hnew = fmaf(z, hreg - n, n);          // (1-z)*n + z*h
            hreg = hnew;
            h_s[nxt][j] = hnew;
            if (write_y)
                y0p[(size_t)t * B_SZ * H_SZ] = hnew;
        }
        __syncthreads();

        xme = nxme;
    }

    // Fused final linear layer (layer 1 only); S_LEN even -> final h in h_s[0]
    if (!write_y && tid < C_SZ) {
        float acc = b_out[tid];
#pragma unroll 8
        for (int k = 0; k < H_SZ; k++)
            acc = fmaf(h_s[0][k], W_out[tid * H_SZ + k], acc);
        out[b * C_SZ + tid] = acc;
    }
}

// ---------------------------------------------------------------------------
extern "C" void kernel_launch(void* const* d_in, const int* in_sizes, int n_in,
                              void* d_out, int out_size)
{
    const float* x     = (const float*)d_in[0];
    const float* W_ih0 = (const float*)d_in[1];
    const float* W_hh0 = (const float*)d_in[2];
    const float* b_ih0 = (const float*)d_in[3];
    const float* b_hh0 = (const float*)d_in[4];
    const float* W_ih1 = (const float*)d_in[5];
    const float* W_hh1 = (const float*)d_in[6];
    const float* b_ih1 = (const float*)d_in[7];
    const float* b_hh1 = (const float*)d_in[8];
    const float* W_out = (const float*)d_in[9];
    const float* b_out = (const float*)d_in[10];
    float* out = (float*)d_out;

    void* xp_ptr = nullptr;
    void* y0_ptr = nullptr;
    cudaGetSymbolAddress(&xp_ptr, g_xp);
    cudaGetSymbolAddress(&y0_ptr, g_y0);
    float* xp = (float*)xp_ptr;
    float* y0 = (float*)y0_ptr;

    cudaFuncSetAttribute(gemm_mma_kernel,
                         cudaFuncAttributeMaxDynamicSharedMemorySize, SM_TOT);

    const dim3 gemm_grid(S_LEN / TCH_T, 3);

    // Layer 0 input projection: x is [B, S, D] -> strideB = S*D, strideT = D
    gemm_mma_kernel<<<gemm_grid, 256, SM_TOT>>>(x, W_ih0, b_ih0, xp,
                                                (long)S_LEN * H_SZ, (long)H_SZ);
    // Layer 0 recurrence (writes y0)
    recur_kernel<<<B_SZ, 512>>>(xp, W_hh0, b_hh0, 1, nullptr, nullptr, nullptr);

    // Layer 1 input projection: y0 is [(t*B + b)*H] -> strideB = H, strideT = B*H
    gemm_mma_kernel<<<gemm_grid, 256, SM_TOT>>>(y0, W_ih1, b_ih1, xp,
                                                (long)H_SZ, (long)B_SZ * H_SZ);
    // Layer 1 recurrence + fused output linear
    recur_kernel<<<B_SZ, 512>>>(xp, W_hh1, b_hh1, 0, W_out, b_out, out);
}

// round 9
// speedup vs baseline: 1.6324x; 1.6324x over previous
#include <cuda_runtime.h>
#include <cuda_bf16.h>
#include <cstdint>

// Problem constants
#define S_LEN 2048
#define B_SZ  128
#define H_SZ  128
#define G_SZ  384   // 3*H
#define C_SZ  10
#define TCH_T 16    // timesteps per GEMM CTA

// Scratch: xp (input projections, reused by both layers) and y0 (layer-0 output seq)
__device__ float g_xp[(size_t)S_LEN * B_SZ * G_SZ];   // [(t*B + b)*3H + g]
__device__ float g_y0[(size_t)S_LEN * B_SZ * H_SZ];   // [(t*B + b)*H + j]

// ---- packed dual-fp32 helpers -------------------------------------------
__device__ __forceinline__ unsigned long long fma2(unsigned long long a,
                                                   unsigned long long b,
                                                   unsigned long long c) {
    unsigned long long d;
    asm("fma.rn.f32x2 %0, %1, %2, %3;" : "=l"(d) : "l"(a), "l"(b), "l"(c));
    return d;
}
__device__ __forceinline__ unsigned long long add2(unsigned long long a,
                                                   unsigned long long b) {
    unsigned long long d;
    asm("add.rn.f32x2 %0, %1, %2;" : "=l"(d) : "l"(a), "l"(b));
    return d;
}
__device__ __forceinline__ float lo32(unsigned long long v) {
    return __uint_as_float((unsigned)(v & 0xffffffffull));
}
__device__ __forceinline__ float hi32(unsigned long long v) {
    return __uint_as_float((unsigned)(v >> 32));
}

// ---- mma.sync / ldmatrix helpers (plain sm_80+ features, no 'a'-gating) ---
__device__ __forceinline__ uint32_t smem_u32(const void* p) {
    uint32_t a;
    asm("{ .reg .u64 t; cvta.to.shared.u64 t, %1; cvt.u32.u64 %0, t; }"
        : "=r"(a) : "l"(p));
    return a;
}
__device__ __forceinline__ void ldmx4(uint32_t* r, uint32_t addr) {
    asm volatile("ldmatrix.sync.aligned.m8n8.x4.shared.b16 {%0,%1,%2,%3}, [%4];"
                 : "=r"(r[0]), "=r"(r[1]), "=r"(r[2]), "=r"(r[3]) : "r"(addr));
}
__device__ __forceinline__ void mma_bf16(float* c, const uint32_t* a,
                                         uint32_t b0, uint32_t b1) {
    asm volatile(
        "mma.sync.aligned.m16n8k16.row.col.f32.bf16.bf16.f32 "
        "{%0,%1,%2,%3}, {%4,%5,%6,%7}, {%8,%9}, {%0,%1,%2,%3};"
        : "+f"(c[0]), "+f"(c[1]), "+f"(c[2]), "+f"(c[3])
        : "r"(a[0]), "r"(a[1]), "r"(a[2]), "r"(a[3]), "r"(b0), "r"(b1));
}

// Split one float4 into bf16 hi + lo pairs (packed as uint2 = 4 bf16)
__device__ __forceinline__ void split4(float4 v, uint2& hi, uint2& lo) {
    __nv_bfloat162 h01 = __floats2bfloat162_rn(v.x, v.y);
    __nv_bfloat162 h23 = __floats2bfloat162_rn(v.z, v.w);
    const float r0 = v.x - __bfloat162float(h01.x);
    const float r1 = v.y - __bfloat162float(h01.y);
    const float r2 = v.z - __bfloat162float(h23.x);
    const float r3 = v.w - __bfloat162float(h23.y);
    __nv_bfloat162 l01 = __floats2bfloat162_rn(r0, r1);
    __nv_bfloat162 l23 = __floats2bfloat162_rn(r2, r3);
    hi = make_uint2(*reinterpret_cast<uint32_t*>(&h01), *reinterpret_cast<uint32_t*>(&h23));
    lo = make_uint2(*reinterpret_cast<uint32_t*>(&l01), *reinterpret_cast<uint32_t*>(&l23));
}

// SMEM layout (bytes): bias + 4 bf16 tiles [128 rows x 128 cols], pitch 272 B
#define PITCHB 272
#define TILEB  (128 * PITCHB)          // 34816
#define SM_BIAS 0
#define SM_XHI  512
#define SM_XLO  (SM_XHI + TILEB)
#define SM_WHI  (SM_XLO + TILEB)
#define SM_WLO  (SM_WHI + TILEB)
#define SM_TOT  (SM_WLO + TILEB)       // 139776

// ---------------------------------------------------------------------------
// Tensor-core input-projection GEMM via mma.sync — unchanged from R7 (proven).
// ---------------------------------------------------------------------------
__global__ __launch_bounds__(256, 1)
void gemm_mma_kernel(const float* __restrict__ in,
                     const float* __restrict__ W,
                     const float* __restrict__ bias,
                     float* __restrict__ out,
                     long strideB, long strideT)
{
    extern __shared__ __align__(16) char smem[];
    const uint32_t sb = smem_u32(smem);
    float* sbias = reinterpret_cast<float*>(smem + SM_BIAS);

    const int tid  = threadIdx.x;
    const int w    = tid >> 5;
    const int lane = tid & 31;
    const int tbase = blockIdx.x * TCH_T;
    const int g0    = blockIdx.y * 128;

    if (tid < 128) sbias[tid] = bias[g0 + tid];
    for (int i = tid; i < 128 * 32; i += 256) {
        const int row = i >> 5, c4 = i & 31;
        const float4 v = *reinterpret_cast<const float4*>(
            W + (size_t)(g0 + row) * H_SZ + c4 * 4);
        uint2 hi, lo;
        split4(v, hi, lo);
        const int off = row * PITCHB + c4 * 8;
        *reinterpret_cast<uint2*>(smem + SM_WHI + off) = hi;
        *reinterpret_cast<uint2*>(smem + SM_WLO + off) = lo;
    }

    const int mBase = (w & 1) * 64;
    const int nBase = (w >> 1) * 32;

    uint32_t aoff[4];
#pragma unroll
    for (int mt = 0; mt < 4; mt++)
        aoff[mt] = (uint32_t)((mBase + mt * 16 + (lane & 15)) * PITCHB
                              + (lane >> 4) * 16);
    uint32_t boff[2];
#pragma unroll
    for (int nt2 = 0; nt2 < 2; nt2++) {
        const int rt = lane & 7, tl = lane >> 3;
        const int n = nBase + nt2 * 16 + ((tl >> 1) << 3) + rt;
        boff[nt2] = (uint32_t)(n * PITCHB + (tl & 1) * 16);
    }

    for (int tt = 0; tt < TCH_T; tt++) {
        const int t = tbase + tt;

        for (int i = tid; i < 128 * 32; i += 256) {
            const int row = i >> 5, c4 = i & 31;
            const float4 v = *reinterpret_cast<const float4*>(
                in + (size_t)row * strideB + (size_t)t * strideT + c4 * 4);
            uint2 hi, lo;
            split4(v, hi, lo);
            const int off = row * PITCHB + c4 * 8;
            *reinterpret_cast<uint2*>(smem + SM_XHI + off) = hi;
            *reinterpret_cast<uint2*>(smem + SM_XLO + off) = lo;
        }
        __syncthreads();

        float acc[4][4][4];
#pragma unroll
        for (int mt = 0; mt < 4; mt++)
#pragma unroll
            for (int nt = 0; nt < 4; nt++)
#pragma unroll
                for (int e = 0; e < 4; e++) acc[mt][nt][e] = 0.0f;

#pragma unroll
        for (int s = 0; s < 3; s++) {
            const uint32_t aS = sb + (s == 2 ? SM_XLO : SM_XHI);
            const uint32_t bS = sb + (s == 1 ? SM_WLO : SM_WHI);
#pragma unroll
            for (int k16 = 0; k16 < 8; k16++) {
                const uint32_t kb = (uint32_t)(k16 * 32);
                uint32_t a[4][4], b[2][4];
#pragma unroll
                for (int mt = 0; mt < 4; mt++) ldmx4(a[mt], aS + aoff[mt] + kb);
#pragma unroll
                for (int nt2 = 0; nt2 < 2; nt2++) ldmx4(b[nt2], bS + boff[nt2] + kb);
#pragma unroll
                for (int mt = 0; mt < 4; mt++)
#pragma unroll
                    for (int nt = 0; nt < 4; nt++)
                        mma_bf16(acc[mt][nt], a[mt],
                                 b[nt >> 1][(nt & 1) * 2], b[nt >> 1][(nt & 1) * 2 + 1]);
            }
        }

        const int mrow = lane >> 2;
        const int ncol = (lane & 3) * 2;
#pragma unroll
        for (int mt = 0; mt < 4; mt++) {
#pragma unroll
            for (int nt = 0; nt < 4; nt++) {
                const int col = nBase + nt * 8 + ncol;
                const float bv0 = sbias[col], bv1 = sbias[col + 1];
                const int row0 = mBase + mt * 16 + mrow;
                float* p0 = out + ((size_t)t * B_SZ + row0) * G_SZ + g0 + col;
                float* p1 = p0 + (size_t)8 * G_SZ;
                *reinterpret_cast<float2*>(p0) =
                    make_float2(acc[mt][nt][0] + bv0, acc[mt][nt][1] + bv1);
                *reinterpret_cast<float2*>(p1) =
                    make_float2(acc[mt][nt][2] + bv0, acc[mt][nt][3] + bv1);
            }
        }
        __syncthreads();
    }
}

// ---------------------------------------------------------------------------
// Recurrent scan (R7 half-split + bank-conflict pad + 3-shfl combine).
// 256 threads, tid = 2*j + p: thread owns the p-th half (64 elems) of all
// three gate rows for output j. h stored with 272B-pitch halves so even/odd
// lane LDS hit disjoint banks. Partial sums exchanged with 2 role-packed
// shfls + 1 for z. Exact activations (__expf + __fdividef -> MUFU RCP).
// ---------------------------------------------------------------------------
#define HP 68   // floats per padded half (64 + 4)

__global__ __launch_bounds__(256, 1)
void recur_kernel(const float* __restrict__ xp,
                  const float* __restrict__ W_hh,
                  const float* __restrict__ b_hh,
                  int write_y,
                  const float* __restrict__ W_out,
                  const float* __restrict__ b_out,
                  float* __restrict__ out)
{
    __shared__ __align__(16) float h_s[2][2 * HP];

    const int b   = blockIdx.x;
    const int tid = threadIdx.x;
    const int j   = tid >> 1;
    const int p   = tid & 1;

    // Weight half-rows -> registers (3 x 32 u64 = 192 regs of weights)
    unsigned long long wr[32], wz[32], wn[32];
    {
        const unsigned long long* rp = reinterpret_cast<const unsigned long long*>(
            W_hh + (size_t)j * H_SZ + p * 64);
        const unsigned long long* zp = reinterpret_cast<const unsigned long long*>(
            W_hh + (size_t)(H_SZ + j) * H_SZ + p * 64);
        const unsigned long long* np = reinterpret_cast<const unsigned long long*>(
            W_hh + (size_t)(2 * H_SZ + j) * H_SZ + p * 64);
#pragma unroll
        for (int i = 0; i < 32; i++) { wr[i] = rp[i]; wz[i] = zp[i]; wn[i] = np[i]; }
    }
    const float br = b_hh[j];
    const float bz = b_hh[H_SZ + j];
    const float bn = b_hh[2 * H_SZ + j];

    const float* xb = xp + (size_t)b * G_SZ;
    // even lane holds xr, xn; odd lane holds xz
    float xr = 0.f, xn = 0.f, xz = 0.f;
    if (p == 0) { xr = __ldg(xb + j); xn = __ldg(xb + 2 * H_SZ + j); }
    else        { xz = __ldg(xb + H_SZ + j); }

    float hreg = 0.0f;
    // padded store slot for hidden index k: k + (k>>6)*4
    if (tid < H_SZ) h_s[0][tid + ((tid >> 6) << 2)] = 0.0f;
    __syncthreads();

    float* y0p = g_y0 + (size_t)b * H_SZ + j;
    const int hslot = j + ((j >> 6) << 2);   // j < 64 always -> hslot == j (p0 writes)

    for (int t = 0; t < S_LEN; t++) {
        const int cur = t & 1;
        const int nxt = cur ^ 1;

        // Prefetch next step's x (consumed next iteration -> hidden)
        float nxr = 0.f, nxn = 0.f, nxz = 0.f;
        if (t + 1 < S_LEN) {
            const float* q = xb + (size_t)(t + 1) * B_SZ * G_SZ;
            if (p == 0) { nxr = __ldg(q + j); nxn = __ldg(q + 2 * H_SZ + j); }
            else        { nxz = __ldg(q + H_SZ + j); }
        }

        // Half-dots: 3 gates x 64 elems = 16 ulonglong2, 6 independent chains
        const ulonglong2* hq =
            reinterpret_cast<const ulonglong2*>(&h_s[cur][p * HP]);
        unsigned long long ar0 = 0ull, ar1 = 0ull;
        unsigned long long az0 = 0ull, az1 = 0ull;
        unsigned long long an0 = 0ull, an1 = 0ull;
#pragma unroll
        for (int i = 0; i < 16; i++) {
            const ulonglong2 q = hq[i];
            ar0 = fma2(q.x, wr[2 * i + 0], ar0);
            ar1 = fma2(q.y, wr[2 * i + 1], ar1);
            az0 = fma2(q.x, wz[2 * i + 0], az0);
            az1 = fma2(q.y, wz[2 * i + 1], az1);
            an0 = fma2(q.x, wn[2 * i + 0], an0);
            an1 = fma2(q.y, wn[2 * i + 1], an1);
        }
        const unsigned long long sr2 = add2(ar0, ar1);
        const unsigned long long sz2 = add2(az0, az1);
        const unsigned long long sn2 = add2(an0, an1);
        const float sr = lo32(sr2) + hi32(sr2);
        const float sz = lo32(sz2) + hi32(sz2);
        const float sn = lo32(sn2) + hi32(sn2);

        // Role-packed exchange: each lane receives exactly what it needs.
        //   shfl1: p0 sends sz (p1 needs it), p1 sends sr (p0 needs it)
        //   shfl2: exchange sn (p0 needs p1's sn)
        const float send1 = (p == 0) ? sz : sr;
        const float recv1 = __shfl_xor_sync(0xffffffffu, send1, 1);
        const float recvn = __shfl_xor_sync(0xffffffffu, sn, 1);

        // pre-activation: r on p0 (xr), z on p1 (xz)
        const float pg = (p == 0) ? (xr + sr + recv1 + br)
                                  : (xz + sz + recv1 + bz);
        const float gv = __fdividef(1.0f, 1.0f + __expf(-pg));  // r (p0) / z (p1)
        const float z  = __shfl_xor_sync(0xffffffffu, gv, 1);   // p0 <- p1's z

        if (p == 0) {
            const float hn = sn + recvn + bn;
            const float ag = fmaf(gv, hn, xn);                  // gv == r
            const float e2 = __expf(-2.0f * ag);
            const float n  = fmaf(-2.0f, __fdividef(e2, 1.0f + e2), 1.0f); // tanh
            const float hnew = fmaf(z, hreg - n, n);            // (1-z)*n + z*h
            hreg = hnew;
            h_s[nxt][hslot] = hnew;
            if (write_y)
                y0p[(size_t)t * B_SZ * H_SZ] = hnew;
        }
        __syncthreads();

        xr = nxr; xn = nxn; xz = nxz;
    }

    // Fused final linear layer (layer 1 only); S_LEN even -> final h in h_s[0]
    if (!write_y && tid < C_SZ) {
        float acc = b_out[tid];
#pragma unroll 8
        for (int k = 0; k < H_SZ; k++)
            acc = fmaf(h_s[0][k + ((k >> 6) << 2)], W_out[tid * H_SZ + k], acc);
        out[b * C_SZ + tid] = acc;
    }
}

// ---------------------------------------------------------------------------
extern "C" void kernel_launch(void* const* d_in, const int* in_sizes, int n_in,
                              void* d_out, int out_size)
{
    const float* x     = (const float*)d_in[0];
    const float* W_ih0 = (const float*)d_in[1];
    const float* W_hh0 = (const float*)d_in[2];
    const float* b_ih0 = (const float*)d_in[3];
    const float* b_hh0 = (const float*)d_in[4];
    const float* W_ih1 = (const float*)d_in[5];
    const float* W_hh1 = (const float*)d_in[6];
    const float* b_ih1 = (const float*)d_in[7];
    const float* b_hh1 = (const float*)d_in[8];
    const float* W_out = (const float*)d_in[9];
    const float* b_out = (const float*)d_in[10];
    float* out = (float*)d_out;

    void* xp_ptr = nullptr;
    void* y0_ptr = nullptr;
    cudaGetSymbolAddress(&xp_ptr, g_xp);
    cudaGetSymbolAddress(&y0_ptr, g_y0);
    float* xp = (float*)xp_ptr;
    float* y0 = (float*)y0_ptr;

    cudaFuncSetAttribute(gemm_mma_kernel,
                         cudaFuncAttributeMaxDynamicSharedMemorySize, SM_TOT);

    const dim3 gemm_grid(S_LEN / TCH_T, 3);

    // Layer 0 input projection: x is [B, S, D] -> strideB = S*D, strideT = D
    gemm_mma_kernel<<<gemm_grid, 256, SM_TOT>>>(x, W_ih0, b_ih0, xp,
                                                (long)S_LEN * H_SZ, (long)H_SZ);
    // Layer 0 recurrence (writes y0)
    recur_kernel<<<B_SZ, 256>>>(xp, W_hh0, b_hh0, 1, nullptr, nullptr, nullptr);

    // Layer 1 input projection: y0 is [(t*B + b)*H] -> strideB = H, strideT = B*H
    gemm_mma_kernel<<<gemm_grid, 256, SM_TOT>>>(y0, W_ih1, b_ih1, xp,
                                                (long)H_SZ, (long)B_SZ * H_SZ);
    // Layer 1 recurrence + fused output linear
    recur_kernel<<<B_SZ, 256>>>(xp, W_hh1, b_hh1, 0, W_out, b_out, out);
}

// round 10
// speedup vs baseline: 1.7660x; 1.0819x over previous
#include <cuda_runtime.h>
#include <cuda_bf16.h>
#include <cstdint>

// Problem constants
#define S_LEN 2048
#define B_SZ  128
#define H_SZ  128
#define G_SZ  384   // 3*H
#define C_SZ  10
#define TCH_T 16    // timesteps per GEMM CTA

// Scratch: xp (input projections, reused by both layers) and y0 (layer-0 output seq)
__device__ float g_xp[(size_t)S_LEN * B_SZ * G_SZ];   // [(t*B + b)*3H + g]
__device__ float g_y0[(size_t)S_LEN * B_SZ * H_SZ];   // [(t*B + b)*H + j]

// ---- packed dual-fp32 helpers -------------------------------------------
__device__ __forceinline__ unsigned long long fma2(unsigned long long a,
                                                   unsigned long long b,
                                                   unsigned long long c) {
    unsigned long long d;
    asm("fma.rn.f32x2 %0, %1, %2, %3;" : "=l"(d) : "l"(a), "l"(b), "l"(c));
    return d;
}
__device__ __forceinline__ unsigned long long add2(unsigned long long a,
                                                   unsigned long long b) {
    unsigned long long d;
    asm("add.rn.f32x2 %0, %1, %2;" : "=l"(d) : "l"(a), "l"(b));
    return d;
}
__device__ __forceinline__ float lo32(unsigned long long v) {
    return __uint_as_float((unsigned)(v & 0xffffffffull));
}
__device__ __forceinline__ float hi32(unsigned long long v) {
    return __uint_as_float((unsigned)(v >> 32));
}

// ---- mma.sync / ldmatrix helpers (plain sm_80+ features, no 'a'-gating) ---
__device__ __forceinline__ uint32_t smem_u32(const void* p) {
    uint32_t a;
    asm("{ .reg .u64 t; cvta.to.shared.u64 t, %1; cvt.u32.u64 %0, t; }"
        : "=r"(a) : "l"(p));
    return a;
}
__device__ __forceinline__ void ldmx4(uint32_t* r, uint32_t addr) {
    asm volatile("ldmatrix.sync.aligned.m8n8.x4.shared.b16 {%0,%1,%2,%3}, [%4];"
                 : "=r"(r[0]), "=r"(r[1]), "=r"(r[2]), "=r"(r[3]) : "r"(addr));
}
__device__ __forceinline__ void mma_bf16(float* c, const uint32_t* a,
                                         uint32_t b0, uint32_t b1) {
    asm volatile(
        "mma.sync.aligned.m16n8k16.row.col.f32.bf16.bf16.f32 "
        "{%0,%1,%2,%3}, {%4,%5,%6,%7}, {%8,%9}, {%0,%1,%2,%3};"
        : "+f"(c[0]), "+f"(c[1]), "+f"(c[2]), "+f"(c[3])
        : "r"(a[0]), "r"(a[1]), "r"(a[2]), "r"(a[3]), "r"(b0), "r"(b1));
}

// Split one float4 into bf16 hi + lo pairs (packed as uint2 = 4 bf16)
__device__ __forceinline__ void split4(float4 v, uint2& hi, uint2& lo) {
    __nv_bfloat162 h01 = __floats2bfloat162_rn(v.x, v.y);
    __nv_bfloat162 h23 = __floats2bfloat162_rn(v.z, v.w);
    const float r0 = v.x - __bfloat162float(h01.x);
    const float r1 = v.y - __bfloat162float(h01.y);
    const float r2 = v.z - __bfloat162float(h23.x);
    const float r3 = v.w - __bfloat162float(h23.y);
    __nv_bfloat162 l01 = __floats2bfloat162_rn(r0, r1);
    __nv_bfloat162 l23 = __floats2bfloat162_rn(r2, r3);
    hi = make_uint2(*reinterpret_cast<uint32_t*>(&h01), *reinterpret_cast<uint32_t*>(&h23));
    lo = make_uint2(*reinterpret_cast<uint32_t*>(&l01), *reinterpret_cast<uint32_t*>(&l23));
}

// SMEM layout (bytes): bias + 2x double-buffered X tiles + W tiles, pitch 272 B
#define PITCHB 272
#define TILEB  (128 * PITCHB)          // 34816
#define SM_BIAS 0
#define SM_XHI0 512
#define SM_XLO0 (SM_XHI0 + TILEB)
#define SM_XHI1 (SM_XLO0 + TILEB)
#define SM_XLO1 (SM_XHI1 + TILEB)
#define SM_WHI  (SM_XLO1 + TILEB)
#define SM_WLO  (SM_WHI + TILEB)
#define SM_TOT  (SM_WLO + TILEB)       // 209408

// ---------------------------------------------------------------------------
// Tensor-core input-projection GEMM via mma.sync, software-pipelined staging:
// next timestep's X tile is LDG'd into registers BEFORE the current MMA block
// (DRAM latency hidden under ~2000 cyc of tensor work), split+STS after.
// ---------------------------------------------------------------------------
__global__ __launch_bounds__(256, 1)
void gemm_mma_kernel(const float* __restrict__ in,
                     const float* __restrict__ W,
                     const float* __restrict__ bias,
                     float* __restrict__ out,
                     long strideB, long strideT)
{
    extern __shared__ __align__(16) char smem[];
    const uint32_t sb = smem_u32(smem);
    float* sbias = reinterpret_cast<float*>(smem + SM_BIAS);

    const int tid  = threadIdx.x;
    const int w    = tid >> 5;
    const int lane = tid & 31;
    const int tbase = blockIdx.x * TCH_T;
    const int g0    = blockIdx.y * 128;

    // Stage W chunk [128 gates x 128 d] hi/lo + bias (once per CTA)
    if (tid < 128) sbias[tid] = bias[g0 + tid];
    for (int i = tid; i < 128 * 32; i += 256) {
        const int row = i >> 5, c4 = i & 31;
        const float4 v = *reinterpret_cast<const float4*>(
            W + (size_t)(g0 + row) * H_SZ + c4 * 4);
        uint2 hi, lo;
        split4(v, hi, lo);
        const int off = row * PITCHB + c4 * 8;
        *reinterpret_cast<uint2*>(smem + SM_WHI + off) = hi;
        *reinterpret_cast<uint2*>(smem + SM_WLO + off) = lo;
    }

    // Per-thread staging indices (16 chunks of 256 threads cover 128x32 float4)
    // chunk k: i = tid + k*256 -> row = i>>5, c4 = i&31
    // Prologue: stage t = tbase into buffer 0
    {
        const int t0 = tbase;
#pragma unroll
        for (int k = 0; k < 16; k++) {
            const int i = tid + k * 256;
            const int row = i >> 5, c4 = i & 31;
            const float4 v = *reinterpret_cast<const float4*>(
                in + (size_t)row * strideB + (size_t)t0 * strideT + c4 * 4);
            uint2 hi, lo;
            split4(v, hi, lo);
            const int off = row * PITCHB + c4 * 8;
            *reinterpret_cast<uint2*>(smem + SM_XHI0 + off) = hi;
            *reinterpret_cast<uint2*>(smem + SM_XLO0 + off) = lo;
        }
    }
    __syncthreads();

    const int mBase = (w & 1) * 64;
    const int nBase = (w >> 1) * 32;

    uint32_t aoff[4];
#pragma unroll
    for (int mt = 0; mt < 4; mt++)
        aoff[mt] = (uint32_t)((mBase + mt * 16 + (lane & 15)) * PITCHB
                              + (lane >> 4) * 16);
    uint32_t boff[2];
#pragma unroll
    for (int nt2 = 0; nt2 < 2; nt2++) {
        const int rt = lane & 7, tl = lane >> 3;
        const int n = nBase + nt2 * 16 + ((tl >> 1) << 3) + rt;
        boff[nt2] = (uint32_t)(n * PITCHB + (tl & 1) * 16);
    }

    for (int tt = 0; tt < TCH_T; tt++) {
        const int t   = tbase + tt;
        const int cur = tt & 1;
        const uint32_t xhiC = cur ? SM_XHI1 : SM_XHI0;
        const uint32_t xloC = cur ? SM_XLO1 : SM_XLO0;
        const uint32_t xhiN = cur ? SM_XHI0 : SM_XHI1;
        const uint32_t xloN = cur ? SM_XLO0 : SM_XLO1;

        // Issue next tile's global loads NOW (consumed after the MMA block)
        float4 v[16];
        const bool more = (tt + 1 < TCH_T);
        if (more) {
#pragma unroll
            for (int k = 0; k < 16; k++) {
                const int i = tid + k * 256;
                const int row = i >> 5, c4 = i & 31;
                v[k] = *reinterpret_cast<const float4*>(
                    in + (size_t)row * strideB + (size_t)(t + 1) * strideT + c4 * 4);
            }
        }

        float acc[4][4][4];
#pragma unroll
        for (int mt = 0; mt < 4; mt++)
#pragma unroll
            for (int nt = 0; nt < 4; nt++)
#pragma unroll
                for (int e = 0; e < 4; e++) acc[mt][nt][e] = 0.0f;

        // 3 splits: Ahi*Whi, Ahi*Wlo, Alo*Whi
#pragma unroll
        for (int s = 0; s < 3; s++) {
            const uint32_t aS = sb + (s == 2 ? xloC : xhiC);
            const uint32_t bS = sb + (s == 1 ? SM_WLO : SM_WHI);
#pragma unroll
            for (int k16 = 0; k16 < 8; k16++) {
                const uint32_t kb = (uint32_t)(k16 * 32);
                uint32_t a[4][4], b[2][4];
#pragma unroll
                for (int mt = 0; mt < 4; mt++) ldmx4(a[mt], aS + aoff[mt] + kb);
#pragma unroll
                for (int nt2 = 0; nt2 < 2; nt2++) ldmx4(b[nt2], bS + boff[nt2] + kb);
#pragma unroll
                for (int mt = 0; mt < 4; mt++)
#pragma unroll
                    for (int nt = 0; nt < 4; nt++)
                        mma_bf16(acc[mt][nt], a[mt],
                                 b[nt >> 1][(nt & 1) * 2], b[nt >> 1][(nt & 1) * 2 + 1]);
            }
        }

        // Split + store next tile (LDG results have arrived under the MMA block)
        if (more) {
#pragma unroll
            for (int k = 0; k < 16; k++) {
                const int i = tid + k * 256;
                const int row = i >> 5, c4 = i & 31;
                uint2 hi, lo;
                split4(v[k], hi, lo);
                const int off = row * PITCHB + c4 * 8;
                *reinterpret_cast<uint2*>(smem + xhiN + off) = hi;
                *reinterpret_cast<uint2*>(smem + xloN + off) = lo;
            }
        }

        // Write out D + bias
        const int mrow = lane >> 2;
        const int ncol = (lane & 3) * 2;
#pragma unroll
        for (int mt = 0; mt < 4; mt++) {
#pragma unroll
            for (int nt = 0; nt < 4; nt++) {
                const int col = nBase + nt * 8 + ncol;
                const float bv0 = sbias[col], bv1 = sbias[col + 1];
                const int row0 = mBase + mt * 16 + mrow;
                float* p0 = out + ((size_t)t * B_SZ + row0) * G_SZ + g0 + col;
                float* p1 = p0 + (size_t)8 * G_SZ;
                *reinterpret_cast<float2*>(p0) =
                    make_float2(acc[mt][nt][0] + bv0, acc[mt][nt][1] + bv1);
                *reinterpret_cast<float2*>(p1) =
                    make_float2(acc[mt][nt][2] + bv0, acc[mt][nt][3] + bv1);
            }
        }
        __syncthreads();   // STS of next buffer complete before it's consumed
    }
}

// ---------------------------------------------------------------------------
// Recurrent scan — EXACT R7 version (proven 1.454 ms/layer).
// 256 threads, tid = 2*j + p: thread owns the p-th half (64 elems) of all
// three gate rows for output j; halves combined via shfl_xor(1).
// ---------------------------------------------------------------------------
__global__ __launch_bounds__(256, 1)
void recur_kernel(const float* __restrict__ xp,
                  const float* __restrict__ W_hh,
                  const float* __restrict__ b_hh,
                  int write_y,
                  const float* __restrict__ W_out,
                  const float* __restrict__ b_out,
                  float* __restrict__ out)
{
    __shared__ __align__(16) float h_s[2][H_SZ];

    const int b   = blockIdx.x;
    const int tid = threadIdx.x;
    const int j   = tid >> 1;
    const int p   = tid & 1;

    unsigned long long wr[32], wz[32], wn[32];
    {
        const unsigned long long* rp = reinterpret_cast<const unsigned long long*>(
            W_hh + (size_t)j * H_SZ + p * 64);
        const unsigned long long* zp = reinterpret_cast<const unsigned long long*>(
            W_hh + (size_t)(H_SZ + j) * H_SZ + p * 64);
        const unsigned long long* np = reinterpret_cast<const unsigned long long*>(
            W_hh + (size_t)(2 * H_SZ + j) * H_SZ + p * 64);
#pragma unroll
        for (int i = 0; i < 32; i++) { wr[i] = rp[i]; wz[i] = zp[i]; wn[i] = np[i]; }
    }
    const float br = b_hh[j];
    const float bz = b_hh[H_SZ + j];
    const float bn = b_hh[2 * H_SZ + j];

    const float* xb = xp + (size_t)b * G_SZ;
    float xr = 0.f, xn = 0.f, xz = 0.f;
    if (p == 0) { xr = __ldg(xb + j); xn = __ldg(xb + 2 * H_SZ + j); }
    else        { xz = __ldg(xb + H_SZ + j); }

    float hreg = 0.0f;
    if (tid < H_SZ) h_s[0][tid] = 0.0f;
    __syncthreads();

    float* y0p = g_y0 + (size_t)b * H_SZ + j;

    for (int t = 0; t < S_LEN; t++) {
        const int cur = t & 1;
        const int nxt = cur ^ 1;

        float nxr = 0.f, nxn = 0.f, nxz = 0.f;
        if (t + 1 < S_LEN) {
            const float* q = xb + (size_t)(t + 1) * B_SZ * G_SZ;
            if (p == 0) { nxr = __ldg(q + j); nxn = __ldg(q + 2 * H_SZ + j); }
            else        { nxz = __ldg(q + H_SZ + j); }
        }

        const ulonglong2* hq =
            reinterpret_cast<const ulonglong2*>(&h_s[cur][p * 64]);
        unsigned long long ar0 = 0ull, ar1 = 0ull;
        unsigned long long az0 = 0ull, az1 = 0ull;
        unsigned long long an0 = 0ull, an1 = 0ull;
#pragma unroll
        for (int i = 0; i < 16; i++) {
            const ulonglong2 q = hq[i];
            ar0 = fma2(q.x, wr[2 * i + 0], ar0);
            ar1 = fma2(q.y, wr[2 * i + 1], ar1);
            az0 = fma2(q.x, wz[2 * i + 0], az0);
            az1 = fma2(q.y, wz[2 * i + 1], az1);
            an0 = fma2(q.x, wn[2 * i + 0], an0);
            an1 = fma2(q.y, wn[2 * i + 1], an1);
        }
        const unsigned long long sr2 = add2(ar0, ar1);
        const unsigned long long sz2 = add2(az0, az1);
        const unsigned long long sn2 = add2(an0, an1);
        float srh = lo32(sr2) + hi32(sr2);
        float szh = lo32(sz2) + hi32(sz2);
        float snh = lo32(sn2) + hi32(sn2);

        srh += __shfl_xor_sync(0xffffffffu, srh, 1);
        szh += __shfl_xor_sync(0xffffffffu, szh, 1);
        snh += __shfl_xor_sync(0xffffffffu, snh, 1);

        const float pr = xr + srh + br;
        const float pz = xz + szh + bz;
        const float rg = 1.0f / (1.0f + __expf(-pr));
        const float zg = 1.0f / (1.0f + __expf(-pz));
        const float z  = __shfl_xor_sync(0xffffffffu, zg, 1);

        if (p == 0) {
            const float hn = snh + bn;
            const float ag = fmaf(rg, hn, xn);
            const float sn = 1.0f / (1.0f + __expf(-2.0f * ag));
            const float n  = fmaf(2.0f, sn, -1.0f);
            const float hnew = fmaf(z, hreg - n, n);
            hreg = hnew;
            h_s[nxt][j] = hnew;
            if (write_y)
                y0p[(size_t)t * B_SZ * H_SZ] = hnew;
        }
        __syncthreads();

        xr = nxr; xn = nxn; xz = nxz;
    }

    if (!write_y && tid < C_SZ) {
        float acc = b_out[tid];
#pragma unroll 8
        for (int k = 0; k < H_SZ; k++)
            acc = fmaf(h_s[0][k], W_out[tid * H_SZ + k], acc);
        out[b * C_SZ + tid] = acc;
    }
}

// ---------------------------------------------------------------------------
extern "C" void kernel_launch(void* const* d_in, const int* in_sizes, int n_in,
                              void* d_out, int out_size)
{
    const float* x     = (const float*)d_in[0];
    const float* W_ih0 = (const float*)d_in[1];
    const float* W_hh0 = (const float*)d_in[2];
    const float* b_ih0 = (const float*)d_in[3];
    const float* b_hh0 = (const float*)d_in[4];
    const float* W_ih1 = (const float*)d_in[5];
    const float* W_hh1 = (const float*)d_in[6];
    const float* b_ih1 = (const float*)d_in[7];
    const float* b_hh1 = (const float*)d_in[8];
    const float* W_out = (const float*)d_in[9];
    const float* b_out = (const float*)d_in[10];
    float* out = (float*)d_out;

    void* xp_ptr = nullptr;
    void* y0_ptr = nullptr;
    cudaGetSymbolAddress(&xp_ptr, g_xp);
    cudaGetSymbolAddress(&y0_ptr, g_y0);
    float* xp = (float*)xp_ptr;
    float* y0 = (float*)y0_ptr;

    cudaFuncSetAttribute(gemm_mma_kernel,
                         cudaFuncAttributeMaxDynamicSharedMemorySize, SM_TOT);

    const dim3 gemm_grid(S_LEN / TCH_T, 3);

    // Layer 0 input projection: x is [B, S, D] -> strideB = S*D, strideT = D
    gemm_mma_kernel<<<gemm_grid, 256, SM_TOT>>>(x, W_ih0, b_ih0, xp,
                                                (long)S_LEN * H_SZ, (long)H_SZ);
    // Layer 0 recurrence (writes y0)
    recur_kernel<<<B_SZ, 256>>>(xp, W_hh0, b_hh0, 1, nullptr, nullptr, nullptr);

    // Layer 1 input projection: y0 is [(t*B + b)*H] -> strideB = H, strideT = B*H
    gemm_mma_kernel<<<gemm_grid, 256, SM_TOT>>>(y0, W_ih1, b_ih1, xp,
                                                (long)H_SZ, (long)B_SZ * H_SZ);
    // Layer 1 recurrence + fused output linear
    recur_kernel<<<B_SZ, 256>>>(xp, W_hh1, b_hh1, 0, W_out, b_out, out);
}

// round 11
// speedup vs baseline: 1.8651x; 1.0561x over previous
#include <cuda_runtime.h>
#include <cuda_bf16.h>
#include <cstdint>

// Problem constants
#define S_LEN 2048
#define B_SZ  128
#define H_SZ  128
#define G_SZ  384   // 3*H
#define C_SZ  10
#define TCH_T 16    // timesteps per GEMM CTA

// Scratch: xp (input projections, reused by both layers) and y0 (layer-0 output seq)
__device__ float g_xp[(size_t)S_LEN * B_SZ * G_SZ];   // [(t*B + b)*3H + g]
__device__ float g_y0[(size_t)S_LEN * B_SZ * H_SZ];   // [(t*B + b)*H + j]

// ---- packed dual-fp32 helpers -------------------------------------------
__device__ __forceinline__ unsigned long long fma2(unsigned long long a,
                                                   unsigned long long b,
                                                   unsigned long long c) {
    unsigned long long d;
    asm("fma.rn.f32x2 %0, %1, %2, %3;" : "=l"(d) : "l"(a), "l"(b), "l"(c));
    return d;
}
__device__ __forceinline__ unsigned long long add2(unsigned long long a,
                                                   unsigned long long b) {
    unsigned long long d;
    asm("add.rn.f32x2 %0, %1, %2;" : "=l"(d) : "l"(a), "l"(b));
    return d;
}
__device__ __forceinline__ float lo32(unsigned long long v) {
    return __uint_as_float((unsigned)(v & 0xffffffffull));
}
__device__ __forceinline__ float hi32(unsigned long long v) {
    return __uint_as_float((unsigned)(v >> 32));
}

// ---- mma.sync / ldmatrix helpers (plain sm_80+ features, no 'a'-gating) ---
__device__ __forceinline__ uint32_t smem_u32(const void* p) {
    uint32_t a;
    asm("{ .reg .u64 t; cvta.to.shared.u64 t, %1; cvt.u32.u64 %0, t; }"
        : "=r"(a) : "l"(p));
    return a;
}
__device__ __forceinline__ void ldmx4(uint32_t* r, uint32_t addr) {
    asm volatile("ldmatrix.sync.aligned.m8n8.x4.shared.b16 {%0,%1,%2,%3}, [%4];"
                 : "=r"(r[0]), "=r"(r[1]), "=r"(r[2]), "=r"(r[3]) : "r"(addr));
}
__device__ __forceinline__ void mma_bf16(float* c, const uint32_t* a,
                                         uint32_t b0, uint32_t b1) {
    asm volatile(
        "mma.sync.aligned.m16n8k16.row.col.f32.bf16.bf16.f32 "
        "{%0,%1,%2,%3}, {%4,%5,%6,%7}, {%8,%9}, {%0,%1,%2,%3};"
        : "+f"(c[0]), "+f"(c[1]), "+f"(c[2]), "+f"(c[3])
        : "r"(a[0]), "r"(a[1]), "r"(a[2]), "r"(a[3]), "r"(b0), "r"(b1));
}

// Split one float4 into bf16 hi + lo pairs (packed as uint2 = 4 bf16)
__device__ __forceinline__ void split4(float4 v, uint2& hi, uint2& lo) {
    __nv_bfloat162 h01 = __floats2bfloat162_rn(v.x, v.y);
    __nv_bfloat162 h23 = __floats2bfloat162_rn(v.z, v.w);
    const float r0 = v.x - __bfloat162float(h01.x);
    const float r1 = v.y - __bfloat162float(h01.y);
    const float r2 = v.z - __bfloat162float(h23.x);
    const float r3 = v.w - __bfloat162float(h23.y);
    __nv_bfloat162 l01 = __floats2bfloat162_rn(r0, r1);
    __nv_bfloat162 l23 = __floats2bfloat162_rn(r2, r3);
    hi = make_uint2(*reinterpret_cast<uint32_t*>(&h01), *reinterpret_cast<uint32_t*>(&h23));
    lo = make_uint2(*reinterpret_cast<uint32_t*>(&l01), *reinterpret_cast<uint32_t*>(&l23));
}

// SMEM layout (bytes): bias + 2x double-buffered X tiles + W tiles, pitch 272 B
#define PITCHB 272
#define TILEB  (128 * PITCHB)          // 34816
#define SM_BIAS 0
#define SM_XHI0 512
#define SM_XLO0 (SM_XHI0 + TILEB)
#define SM_XHI1 (SM_XLO0 + TILEB)
#define SM_XLO1 (SM_XHI1 + TILEB)
#define SM_WHI  (SM_XLO1 + TILEB)
#define SM_WLO  (SM_WHI + TILEB)
#define SM_TOT  (SM_WLO + TILEB)       // 209408

// ---------------------------------------------------------------------------
// Tensor-core input-projection GEMM via mma.sync, software-pipelined staging
// AND double-buffered ldmatrix fragments (k16+1 frags load under k16 HMMAs).
// ---------------------------------------------------------------------------
__global__ __launch_bounds__(256, 1)
void gemm_mma_kernel(const float* __restrict__ in,
                     const float* __restrict__ W,
                     const float* __restrict__ bias,
                     float* __restrict__ out,
                     long strideB, long strideT)
{
    extern __shared__ __align__(16) char smem[];
    const uint32_t sb = smem_u32(smem);
    float* sbias = reinterpret_cast<float*>(smem + SM_BIAS);

    const int tid  = threadIdx.x;
    const int w    = tid >> 5;
    const int lane = tid & 31;
    const int tbase = blockIdx.x * TCH_T;
    const int g0    = blockIdx.y * 128;

    // Stage W chunk [128 gates x 128 d] hi/lo + bias (once per CTA)
    if (tid < 128) sbias[tid] = bias[g0 + tid];
    for (int i = tid; i < 128 * 32; i += 256) {
        const int row = i >> 5, c4 = i & 31;
        const float4 v = *reinterpret_cast<const float4*>(
            W + (size_t)(g0 + row) * H_SZ + c4 * 4);
        uint2 hi, lo;
        split4(v, hi, lo);
        const int off = row * PITCHB + c4 * 8;
        *reinterpret_cast<uint2*>(smem + SM_WHI + off) = hi;
        *reinterpret_cast<uint2*>(smem + SM_WLO + off) = lo;
    }

    // Prologue: stage t = tbase into buffer 0
    {
        const int t0 = tbase;
#pragma unroll
        for (int k = 0; k < 16; k++) {
            const int i = tid + k * 256;
            const int row = i >> 5, c4 = i & 31;
            const float4 v = *reinterpret_cast<const float4*>(
                in + (size_t)row * strideB + (size_t)t0 * strideT + c4 * 4);
            uint2 hi, lo;
            split4(v, hi, lo);
            const int off = row * PITCHB + c4 * 8;
            *reinterpret_cast<uint2*>(smem + SM_XHI0 + off) = hi;
            *reinterpret_cast<uint2*>(smem + SM_XLO0 + off) = lo;
        }
    }
    __syncthreads();

    const int mBase = (w & 1) * 64;
    const int nBase = (w >> 1) * 32;

    uint32_t aoff[4];
#pragma unroll
    for (int mt = 0; mt < 4; mt++)
        aoff[mt] = (uint32_t)((mBase + mt * 16 + (lane & 15)) * PITCHB
                              + (lane >> 4) * 16);
    uint32_t boff[2];
#pragma unroll
    for (int nt2 = 0; nt2 < 2; nt2++) {
        const int rt = lane & 7, tl = lane >> 3;
        const int n = nBase + nt2 * 16 + ((tl >> 1) << 3) + rt;
        boff[nt2] = (uint32_t)(n * PITCHB + (tl & 1) * 16);
    }

    for (int tt = 0; tt < TCH_T; tt++) {
        const int t   = tbase + tt;
        const int cur = tt & 1;
        const uint32_t xhiC = cur ? SM_XHI1 : SM_XHI0;
        const uint32_t xloC = cur ? SM_XLO1 : SM_XLO0;
        const uint32_t xhiN = cur ? SM_XHI0 : SM_XHI1;
        const uint32_t xloN = cur ? SM_XLO0 : SM_XLO1;

        // Issue next tile's global loads NOW (consumed after the MMA block)
        float4 v[16];
        const bool more = (tt + 1 < TCH_T);
        if (more) {
#pragma unroll
            for (int k = 0; k < 16; k++) {
                const int i = tid + k * 256;
                const int row = i >> 5, c4 = i & 31;
                v[k] = *reinterpret_cast<const float4*>(
                    in + (size_t)row * strideB + (size_t)(t + 1) * strideT + c4 * 4);
            }
        }

        float acc[4][4][4];
#pragma unroll
        for (int mt = 0; mt < 4; mt++)
#pragma unroll
            for (int nt = 0; nt < 4; nt++)
#pragma unroll
                for (int e = 0; e < 4; e++) acc[mt][nt][e] = 0.0f;

        // 3 splits: Ahi*Whi, Ahi*Wlo, Alo*Whi.
        // Within each split: double-buffered frags — load k16+1 while k16 MMAs issue.
#pragma unroll
        for (int s = 0; s < 3; s++) {
            const uint32_t aS = sb + (s == 2 ? xloC : xhiC);
            const uint32_t bS = sb + (s == 1 ? SM_WLO : SM_WHI);

            uint32_t a[2][4][4], b[2][2][4];
            // prologue: k16 = 0 frags
#pragma unroll
            for (int mt = 0; mt < 4; mt++) ldmx4(a[0][mt], aS + aoff[mt]);
#pragma unroll
            for (int nt2 = 0; nt2 < 2; nt2++) ldmx4(b[0][nt2], bS + boff[nt2]);

#pragma unroll
            for (int k16 = 0; k16 < 8; k16++) {
                const int pc = k16 & 1;        // current buffer
                const int pn = pc ^ 1;         // next buffer
                if (k16 < 7) {
                    const uint32_t kb = (uint32_t)((k16 + 1) * 32);
#pragma unroll
                    for (int mt = 0; mt < 4; mt++) ldmx4(a[pn][mt], aS + aoff[mt] + kb);
#pragma unroll
                    for (int nt2 = 0; nt2 < 2; nt2++) ldmx4(b[pn][nt2], bS + boff[nt2] + kb);
                }
#pragma unroll
                for (int mt = 0; mt < 4; mt++)
#pragma unroll
                    for (int nt = 0; nt < 4; nt++)
                        mma_bf16(acc[mt][nt], a[pc][mt],
                                 b[pc][nt >> 1][(nt & 1) * 2],
                                 b[pc][nt >> 1][(nt & 1) * 2 + 1]);
            }
        }

        // Split + store next tile (LDG results arrived under the MMA block)
        if (more) {
#pragma unroll
            for (int k = 0; k < 16; k++) {
                const int i = tid + k * 256;
                const int row = i >> 5, c4 = i & 31;
                uint2 hi, lo;
                split4(v[k], hi, lo);
                const int off = row * PITCHB + c4 * 8;
                *reinterpret_cast<uint2*>(smem + xhiN + off) = hi;
                *reinterpret_cast<uint2*>(smem + xloN + off) = lo;
            }
        }

        // Write out D + bias
        const int mrow = lane >> 2;
        const int ncol = (lane & 3) * 2;
#pragma unroll
        for (int mt = 0; mt < 4; mt++) {
#pragma unroll
            for (int nt = 0; nt < 4; nt++) {
                const int col = nBase + nt * 8 + ncol;
                const float bv0 = sbias[col], bv1 = sbias[col + 1];
                const int row0 = mBase + mt * 16 + mrow;
                float* p0 = out + ((size_t)t * B_SZ + row0) * G_SZ + g0 + col;
                float* p1 = p0 + (size_t)8 * G_SZ;
                *reinterpret_cast<float2*>(p0) =
                    make_float2(acc[mt][nt][0] + bv0, acc[mt][nt][1] + bv1);
                *reinterpret_cast<float2*>(p1) =
                    make_float2(acc[mt][nt][2] + bv0, acc[mt][nt][3] + bv1);
            }
        }
        __syncthreads();   // STS of next buffer complete before it's consumed
    }
}

// ---------------------------------------------------------------------------
// Recurrent scan — EXACT Round-1 version (measured best: 1.355 ms/layer).
// One CTA per batch element, 384 threads (one per gate output).
// Thread g holds W_hh[g][:] (128 fp32) in registers. Per step:
//   hp[g] = h . W_hh[g] + b_hh[g]   (f32x2 FMA, h via broadcast LDS.128)
//   gates computed by threads 0..127, h updated in smem.
// ---------------------------------------------------------------------------
__global__ __launch_bounds__(384, 1)
void recur_kernel(const float* __restrict__ xp,
                  const float* __restrict__ W_hh,
                  const float* __restrict__ b_hh,
                  int write_y,
                  const float* __restrict__ W_out,
                  const float* __restrict__ b_out,
                  float* __restrict__ out)
{
    __shared__ __align__(16) float h_s[H_SZ];
    __shared__ float hp_s[G_SZ];
    __shared__ float xg_s[G_SZ];

    const int b = blockIdx.x;
    const int g = threadIdx.x;

    unsigned long long w[64];
    const unsigned long long* wrow =
        reinterpret_cast<const unsigned long long*>(W_hh + (size_t)g * H_SZ);
#pragma unroll
    for (int i = 0; i < 64; i++) w[i] = wrow[i];
    const float bh = b_hh[g];

    if (g < H_SZ) h_s[g] = 0.0f;

    const float* xptr = xp + (size_t)b * G_SZ + g;
    float xnext = __ldg(xptr);        // prefetch t=0
    __syncthreads();

    for (int t = 0; t < S_LEN; t++) {
        const float xcur = xnext;
        if (t + 1 < S_LEN)
            xnext = __ldg(xptr + (size_t)(t + 1) * B_SZ * G_SZ);  // prefetch next step

        // hp[g] = h . W_hh[g]
        unsigned long long a0 = 0ull, a1 = 0ull;
        const ulonglong2* hq = reinterpret_cast<const ulonglong2*>(h_s);
#pragma unroll
        for (int i = 0; i < 32; i++) {
            const ulonglong2 q = hq[i];   // broadcast LDS.128
            a0 = fma2(q.x, w[2 * i + 0], a0);
            a1 = fma2(q.y, w[2 * i + 1], a1);
        }
        hp_s[g] = lo32(a0) + hi32(a0) + lo32(a1) + hi32(a1) + bh;
        xg_s[g] = xcur;
        __syncthreads();

        if (g < H_SZ) {
            const float pr = xg_s[g]            + hp_s[g];
            const float pz = xg_s[H_SZ + g]     + hp_s[H_SZ + g];
            const float xn = xg_s[2 * H_SZ + g];
            const float hn = hp_s[2 * H_SZ + g];
            const float r = 1.0f / (1.0f + __expf(-pr));
            const float z = 1.0f / (1.0f + __expf(-pz));
            const float n = tanhf(fmaf(r, hn, xn));
            const float hold = h_s[g];
            const float hnew = (1.0f - z) * n + z * hold;
            h_s[g] = hnew;
            if (write_y)
                g_y0[((size_t)t * B_SZ + b) * H_SZ + g] = hnew;
        }
        __syncthreads();
    }

    // Fused final linear layer (layer 1 only)
    if (!write_y && g < C_SZ) {
        float acc = b_out[g];
#pragma unroll 8
        for (int j = 0; j < H_SZ; j++)
            acc = fmaf(h_s[j], W_out[g * H_SZ + j], acc);
        out[b * C_SZ + g] = acc;
    }
}

// ---------------------------------------------------------------------------
extern "C" void kernel_launch(void* const* d_in, const int* in_sizes, int n_in,
                              void* d_out, int out_size)
{
    const float* x     = (const float*)d_in[0];
    const float* W_ih0 = (const float*)d_in[1];
    const float* W_hh0 = (const float*)d_in[2];
    const float* b_ih0 = (const float*)d_in[3];
    const float* b_hh0 = (const float*)d_in[4];
    const float* W_ih1 = (const float*)d_in[5];
    const float* W_hh1 = (const float*)d_in[6];
    const float* b_ih1 = (const float*)d_in[7];
    const float* b_hh1 = (const float*)d_in[8];
    const float* W_out = (const float*)d_in[9];
    const float* b_out = (const float*)d_in[10];
    float* out = (float*)d_out;

    void* xp_ptr = nullptr;
    void* y0_ptr = nullptr;
    cudaGetSymbolAddress(&xp_ptr, g_xp);
    cudaGetSymbolAddress(&y0_ptr, g_y0);
    float* xp = (float*)xp_ptr;
    float* y0 = (float*)y0_ptr;

    cudaFuncSetAttribute(gemm_mma_kernel,
                         cudaFuncAttributeMaxDynamicSharedMemorySize, SM_TOT);

    const dim3 gemm_grid(S_LEN / TCH_T, 3);

    // Layer 0 input projection: x is [B, S, D] -> strideB = S*D, strideT = D
    gemm_mma_kernel<<<gemm_grid, 256, SM_TOT>>>(x, W_ih0, b_ih0, xp,
                                                (long)S_LEN * H_SZ, (long)H_SZ);
    // Layer 0 recurrence (writes y0)
    recur_kernel<<<B_SZ, 384>>>(xp, W_hh0, b_hh0, 1, nullptr, nullptr, nullptr);

    // Layer 1 input projection: y0 is [(t*B + b)*H] -> strideB = H, strideT = B*H
    gemm_mma_kernel<<<gemm_grid, 256, SM_TOT>>>(y0, W_ih1, b_ih1, xp,
                                                (long)H_SZ, (long)B_SZ * H_SZ);
    // Layer 1 recurrence + fused output linear
    recur_kernel<<<B_SZ, 384>>>(xp, W_hh1, b_hh1, 0, W_out, b_out, out);
}